// round 13
// baseline (speedup 1.0000x reference)
#include <cuda_runtime.h>

#define N_ANCH 1000
#define N_FEAT 78
#define NT     256
#define NCTA   512          // 64 images * 8 CTAs; CTA = slice for stage-1, 2 priors for select
#define K_MAX  64
#define FULL   0xffffffffu
#define NIMG   64
#define SLICE  125

__device__ float    gA[(size_t)NIMG * 16 * 1000];
__device__ float    gLiou[(size_t)NIMG * 16 * 1000];
__device__ float    gLogit[(size_t)NIMG * 2 * 1024];
__device__ float    gSums[(size_t)NIMG * 8 * 68];
__device__ float    g_part[1024 * 3];
__device__ unsigned g_ctr;
__device__ unsigned g_imgc[NIMG];

static __device__ __forceinline__ unsigned fkey(float f) {
    unsigned u = __float_as_uint(f);
    return (u & 0x80000000u) ? ~u : (u | 0x80000000u);
}
static __device__ __forceinline__ float wsum(float v) {
    #pragma unroll
    for (int o = 16; o; o >>= 1) v += __shfl_xor_sync(FULL, v, o);
    return v;
}
static __device__ __forceinline__ float wmax(float v) {
    #pragma unroll
    for (int o = 16; o; o >>= 1) v = fmaxf(v, __shfl_xor_sync(FULL, v, o));
    return v;
}
static __device__ __forceinline__ int wscan_incl(int v, int lane) {
    #pragma unroll
    for (int o = 1; o < 32; o <<= 1) {
        int t = __shfl_up_sync(FULL, v, o);
        if (lane >= o) v += t;
    }
    return v;
}

#define GBAR() asm volatile("bar.sync %0, 128;" :: "r"(wg + 1) : "memory")

// dynamic smem layout (floats):
//   tile  [0     .. 9000)   125 anchors x 72 feats, stride 72 (16B-aligned rows)
//   Lbuf  [9000  .. 11048)  16 priors x 128 anchors (p-major)
//   spsmL [11048 .. 12200)  16 priors x 72 feats (feature section, 16B-aligned)
//   spH   [12200 .. 12328)  16 priors x 8 (header cols 0..5)
//   hc0/hc1/hx/hy/ht [12328 .. 12968)  5 x 128 header columns
//   Phase B aliases: f0s[0..1000) f1s[1000..2000) Acst[2000..4000)  (spH stays live)
#define OFF_LBUF  9000
#define OFF_SPL   11048
#define OFF_SPH   12200
#define OFF_HC0   12328
#define OFF_HC1   12456
#define OFF_HX    12584
#define OFF_HY    12712
#define OFF_HT    12840
#define DYN_FLOATS 12968

__global__ __launch_bounds__(NT, 4)
void lane_kernel(const float* __restrict__ output, const float* __restrict__ label,
                 float* __restrict__ out)
{
    extern __shared__ float dyn[];
    float* tile  = dyn;
    float* Lbuf  = dyn + OFF_LBUF;
    float* spsmL = dyn + OFF_SPL;
    float* spH   = dyn + OFF_SPH;
    float* hc0   = dyn + OFF_HC0;
    float* hc1   = dyn + OFF_HC1;
    float* hx    = dyn + OFF_HX;
    float* hy    = dyn + OFF_HY;
    float* ht    = dyn + OFF_HT;

    __shared__ float wred[12 * 8];
    __shared__ float bres[12];
    __shared__ unsigned sAm;
    __shared__ int   hist2[2][256];
    __shared__ int   iw2[2][4];
    __shared__ int   sel2[2][K_MAX];
    __shared__ int   si22[2][2];
    __shared__ float wred2[2][16];
    __shared__ float bres22[2][4];
    __shared__ int   tbuf[2][64];
    __shared__ int   tcnt[2];

    const int tid = threadIdx.x;
    const int wid = tid >> 5;
    const int l   = tid & 31;
    const int bx  = blockIdx.x;
    const int img = bx >> 3;
    const int sl  = bx & 7;
    const float* feat = output + (size_t)img * (N_ANCH * N_FEAT);

    // ---------------- priors: feature section (shifted, aligned) + header
    for (int idx = tid; idx < 16 * 72; idx += NT) {
        int p = idx / 72, j = idx - p * 72;
        spsmL[idx] = label[((size_t)img * 16 + p) * N_FEAT + 6 + j];
    }
    if (tid < 128) {
        int p = tid >> 3, c = tid & 7;
        if (c < 6) spH[tid] = label[((size_t)img * 16 + p) * N_FEAT + c];
    }

    // ---------------- tile fill: warp-per-anchor, coalesced; headers split out
    for (int a = wid; a < SLICE; a += 8) {
        const float* src = feat + (size_t)(sl * SLICE + a) * N_FEAT;
        float v0 = src[l];
        float v1 = src[32 + l];
        if (l >= 6) tile[a * 72 + l - 6] = v0;
        else {
            if (l == 0) hc0[a] = v0;
            else if (l == 1) hc1[a] = v0;
            else if (l == 3) hx[a] = v0;
            else if (l == 4) hy[a] = v0;
            else if (l == 5) ht[a] = v0;
        }
        tile[a * 72 + 26 + l] = v1;
        if (l < 14) tile[a * 72 + 58 + l] = src[64 + l];
    }
    __syncthreads();

    // ---------------- logits out + slice max
    float m0 = -3.4e38f, m1 = -3.4e38f;
    if (tid < SLICE) {
        float v0 = hc0[tid], v1 = hc1[tid];
        gLogit[((size_t)img * 2 + 0) * 1024 + sl * SLICE + tid] = v0;
        gLogit[((size_t)img * 2 + 1) * 1024 + sl * SLICE + tid] = v1;
        m0 = v0; m1 = v1;
    }
    {
        float v;
        v = wmax(m0); if (l == 0) wred[0 * 8 + wid] = v;
        v = wmax(m1); if (l == 0) wred[1 * 8 + wid] = v;
    }

    // ---------------- L1 for 16 priors: half-anchor per thread, all LDS.128
    int a = tid >> 1; if (a > SLICE - 1) a = SLICE - 1;
    const int h = tid & 1;
    const int jr0 = 36 * h;
    float L[16];
    #pragma unroll
    for (int p = 0; p < 16; ++p) L[p] = 0.f;
    {
        const float* vrow = tile + a * 72 + jr0;
        const float* spb  = spsmL + jr0;
        #pragma unroll 3
        for (int c = 0; c < 9; ++c) {
            float4 v = *(const float4*)(vrow + 4 * c);
            #pragma unroll
            for (int p = 0; p < 16; ++p) {
                float4 s = *(const float4*)(spb + p * 72 + 4 * c);
                L[p] += fabsf(v.x - s.x) + fabsf(v.y - s.y)
                      + fabsf(v.z - s.z) + fabsf(v.w - s.w);
            }
        }
    }
    #pragma unroll
    for (int p = 0; p < 16; ++p) L[p] += __shfl_xor_sync(FULL, L[p], 1);
    if (h == 0 && tid < 2 * SLICE) {
        #pragma unroll
        for (int p = 0; p < 16; ++p) Lbuf[p * 128 + a] = L[p];
    }
    __syncthreads();

    if (tid < 2) {
        float r = wred[tid * 8];
        for (int w = 1; w < 8; ++w) r = fmaxf(r, wred[tid * 8 + w]);
        gSums[((size_t)img * 8 + sl) * 68 + tid] = r;
    }

    // ---------------- per-prior products + slice partial sums (warp w: p = w, w+8)
    {
        #pragma unroll
        for (int pi = 0; pi < 2; ++pi) {
            const int p = wid + 8 * pi;
            const float px = spH[p * 8 + 3], py = spH[p * 8 + 4], pt = spH[p * 8 + 5];
            float sxy = 0.f, sth = 0.f, sdis = 0.f, sliou = 0.f;
            #pragma unroll
            for (int m = 0; m < 4; ++m) {
                int a2 = l + 32 * m;
                if (a2 < SLICE) {
                    float Lv = Lbuf[p * 128 + a2];
                    float rx = hx[a2], ry = hy[a2], rt = ht[a2];
                    float dx = rx - px, dy = ry - py, th = rt - pt;
                    float xy = sqrtf(dx * dx + dy * dy);
                    float dis = Lv * (1.0f / 72.0f);
                    float liou = __fdividef(2.f * Lv + 1e-9f, 2160.f + Lv + 1e-9f);
                    size_t o = ((size_t)img * 16 + p) * 1000 + sl * SLICE + a2;
                    gA[o] = dis * xy * th;
                    gLiou[o] = liou;
                    sxy += xy * xy; sth += th * th; sdis += dis * dis; sliou += liou;
                }
            }
            sxy = wsum(sxy); sth = wsum(sth); sdis = wsum(sdis); sliou = wsum(sliou);
            if (l == 0) {
                float* gs = gSums + ((size_t)img * 8 + sl) * 68 + 2 + p * 4;
                gs[0] = sxy; gs[1] = sth; gs[2] = sdis; gs[3] = sliou;
            }
        }
    }

    // ---------------- per-image generation barrier
    __threadfence();
    __syncthreads();
    if (tid == 0) {
        unsigned old = atomicAdd(&g_imgc[img], 1u);
        unsigned target = ((old >> 3) + 1u) << 3;
        unsigned v;
        do {
            asm volatile("ld.acquire.gpu.u32 %0, [%1];"
                         : "=r"(v) : "l"(g_imgc + img) : "memory");
            if (v >= target) break;
            __nanosleep(40);
        } while (true);
        __threadfence();
    }
    __syncthreads();

    // ================ Phase B: totals, softmax, focal =========================
    float* f0s  = dyn;
    float* f1s  = dyn + 1000;
    float* Acst = dyn + 2000;

    if (tid < 2) {
        float m = -3.4e38f;
        for (int s = 0; s < 8; ++s) m = fmaxf(m, gSums[((size_t)img * 8 + s) * 68 + tid]);
        bres[tid] = m;
    } else if (tid >= 32 && tid < 40) {
        int q = tid - 32;
        int p = 2 * sl + (q >> 2), c = q & 3;
        float t = 0.f;
        for (int s = 0; s < 8; ++s) t += gSums[((size_t)img * 8 + s) * 68 + 2 + p * 4 + c];
        bres[2 + q] = t;
    }
    __syncthreads();
    const float M0 = bres[0], M1 = bres[1];

    const float* gl0 = gLogit + ((size_t)img * 2 + 0) * 1024;
    const float* gl1 = gLogit + ((size_t)img * 2 + 1) * 1024;
    const bool act = (tid < 250);
    float s0 = 0.f, s1 = 0.f;
    if (act) {
        float4 c = ((const float4*)gl0)[tid];
        ((float4*)f0s)[tid] = c;
        s0 = expf(c.x - M0) + expf(c.y - M0) + expf(c.z - M0) + expf(c.w - M0);
        float4 d = ((const float4*)gl1)[tid];
        ((float4*)f1s)[tid] = d;
        s1 = expf(d.x - M1) + expf(d.y - M1) + expf(d.z - M1) + expf(d.w - M1);
    }
    {
        float v;
        v = wsum(s0); if (l == 0) wred[0 * 8 + wid] = v;
        v = wsum(s1); if (l == 0) wred[1 * 8 + wid] = v;
        __syncthreads();
        if (tid < 2) {
            float r = 0.f;
            for (int w = 0; w < 8; ++w) r += wred[tid * 8 + w];
            bres[10 + tid] = r;
        }
        __syncthreads();
    }
    const float lse0 = M0 + logf(bres[10]);
    const float lse1 = M1 + logf(bres[11]);

    if (act) {
        float4 c = ((const float4*)f0s)[tid];
        float ls, e;
        ls = c.x - lse0; e = expf(ls); c.x = (1.f - e) * (1.f - e) * ls;
        ls = c.y - lse0; e = expf(ls); c.y = (1.f - e) * (1.f - e) * ls;
        ls = c.z - lse0; e = expf(ls); c.z = (1.f - e) * (1.f - e) * ls;
        ls = c.w - lse0; e = expf(ls); c.w = (1.f - e) * (1.f - e) * ls;
        ((float4*)f0s)[tid] = c;
        float4 d = ((const float4*)f1s)[tid];
        ls = d.x - lse1; e = expf(ls); d.x = (1.f - e) * (1.f - e) * ls;
        ls = d.y - lse1; e = expf(ls); d.y = (1.f - e) * (1.f - e) * ls;
        ls = d.z - lse1; e = expf(ls); d.z = (1.f - e) * (1.f - e) * ls;
        ls = d.w - lse1; e = expf(ls); d.w = (1.f - e) * (1.f - e) * ls;
        ((float4*)f1s)[tid] = d;
    }
    __syncthreads();

    // ================ SPLIT: group wg handles prior 2*sl+wg ===================
    const int wg = wid >> 2;
    const int lt = tid & 127;
    const int lw = (tid >> 5) & 3;
    const int prior = 2 * sl + wg;

    const float sxy   = bres[2 + wg * 4 + 0];
    const float sth   = bres[2 + wg * 4 + 1];
    const float sdis  = bres[2 + wg * 4 + 2];
    const float sliou = bres[2 + wg * 4 + 3];
    const float Nx  = fmaxf(sqrtf(sxy),  1e-12f);
    const float Nt2 = fmaxf(sqrtf(sth),  1e-12f);
    const float Nd  = fmaxf(sqrtf(sdis), 1e-12f);
    const float invn = 1.f / (Nx * Nt2 * Nd);
    int k = (int)sliou;
    if (k < 1) k = 1;
    if (k > K_MAX) k = K_MAX;
    const float* spl = spH + prior * 8;
    const float pr0 = spl[0], pr1 = spl[1];
    const float* gAp = gA    + ((size_t)img * 16 + prior) * 1000;
    const float* gLp = gLiou + ((size_t)img * 16 + prior) * 1000;
    float* Ac = Acst + wg * 1000;

    hist2[wg][lt] = 0; hist2[wg][lt + 128] = 0;
    unsigned keys[8];
    #pragma unroll
    for (int q = 0; q < 8; ++q) {
        int i = lt + (q << 7);
        if (i < N_ANCH) {
            float av = gAp[i];
            float t = av * invn;
            float cost = 3.f * t * t + pr0 * f0s[i] + pr1 * f1s[i];
            Ac[i] = cost;
            keys[q] = fkey(cost);
        } else keys[q] = 0xFFFFFFFFu;
    }
    GBAR();

    // ---------------- radix-select k-th smallest (4x8-bit)
    unsigned prefix = 0; int kk = k;
    #pragma unroll
    for (int shift = 24; shift >= 0; shift -= 8) {
        unsigned pmask = (shift == 24) ? 0u : (0xFFFFFFFFu << (shift + 8));
        #pragma unroll
        for (int q = 0; q < 8; ++q) {
            int i = lt + (q << 7);
            if (i < N_ANCH && (keys[q] & pmask) == prefix)
                atomicAdd(&hist2[wg][(keys[q] >> shift) & 255], 1);
        }
        GBAR();
        if (lw == 0) {
            int b[8]; int s = 0;
            #pragma unroll
            for (int t2 = 0; t2 < 8; ++t2) {
                b[t2] = hist2[wg][l * 8 + t2];
                s += b[t2];
                hist2[wg][l * 8 + t2] = 0;
            }
            int incl = wscan_incl(s, l);
            int excl = incl - s;
            if (kk > excl && kk <= incl) {
                int run = excl, bin = -1, rem = 0;
                #pragma unroll
                for (int t2 = 0; t2 < 8; ++t2) {
                    if (bin < 0 && kk <= run + b[t2]) { bin = l * 8 + t2; rem = kk - run; }
                    run += b[t2];
                }
                si22[wg][0] = bin; si22[wg][1] = rem;
            }
        }
        GBAR();
        prefix |= ((unsigned)si22[wg][0]) << shift;
        kk = si22[wg][1];
    }
    const unsigned T = prefix;
    const int rties = kk;

    // ---------------- tie collection (exact semantics)
    if (lt == 0) tcnt[wg] = 0;
    GBAR();
    #pragma unroll
    for (int q = 0; q < 8; ++q) {
        int i = lt + (q << 7);
        if (i < N_ANCH && keys[q] == T) {
            int p = atomicAdd(&tcnt[wg], 1);
            if (p < 64) tbuf[wg][p] = i;
        }
    }
    GBAR();
    const int nt = tcnt[wg];

    auto pick = [&](int q) -> bool {
        int i = lt + (q << 7);
        if (i >= N_ANCH) return false;
        unsigned key = keys[q];
        if (key < T) return true;
        if (key != T) return false;
        int r = 0;
        if (nt <= 64) {
            for (int t2 = 0; t2 < nt; ++t2) r += (tbuf[wg][t2] < i);
        } else {
            for (int j = 0; j < i; ++j) r += (fkey(Ac[j]) == T);
        }
        return r < rties;
    };

    // ---------------- deterministic compaction
    int cnt = 0;
    #pragma unroll
    for (int q = 0; q < 8; ++q) cnt += pick(q) ? 1 : 0;
    {
        int inc = wscan_incl(cnt, l);
        if (l == 31) iw2[wg][lw] = inc;
        GBAR();
        int off = 0;
        #pragma unroll
        for (int w = 0; w < 4; ++w) if (w < lw) off += iw2[wg][w];
        int o = off + inc - cnt;
        #pragma unroll
        for (int q = 0; q < 8; ++q)
            if (pick(q)) sel2[wg][o++] = lt + (q << 7);
    }
    GBAR();

    // ---------------- stage-2: one scattered row read (cols 0..5) + liou gather
    float q2 = 0.f, q3 = 0.f, q4 = 0.f, q5 = 0.f;
    float2 h0, h1, h2;
    int si = 0;
    if (lt < k) {
        si = sel2[wg][lt];
        const float2* row2 = (const float2*)(feat + (size_t)si * N_FEAT);
        h0 = row2[0]; h1 = row2[1]; h2 = row2[2];
        q2 = h1.x * h1.x; q3 = h1.y * h1.y; q4 = h2.x * h2.x; q5 = h2.y * h2.y;
    }
    {
        float v;
        v = wsum(q2); if (l == 0) wred2[wg][0 * 4 + lw] = v;
        v = wsum(q3); if (l == 0) wred2[wg][1 * 4 + lw] = v;
        v = wsum(q4); if (l == 0) wred2[wg][2 * 4 + lw] = v;
        v = wsum(q5); if (l == 0) wred2[wg][3 * 4 + lw] = v;
        GBAR();
        if (lt < 4) {
            float r = 0.f;
            for (int w = 0; w < 4; ++w) r += wred2[wg][lt * 4 + w];
            bres22[wg][lt] = r;
        }
        GBAR();
    }
    const float inv2 = __fdividef(1.f, fmaxf(sqrtf(bres22[wg][0] + spl[2] * spl[2]), 1e-12f));
    const float inv3 = __fdividef(1.f, fmaxf(sqrtf(bres22[wg][1] + spl[3] * spl[3]), 1e-12f));
    const float inv4 = __fdividef(1.f, fmaxf(sqrtf(bres22[wg][2] + spl[4] * spl[4]), 1e-12f));
    const float inv5 = __fdividef(1.f, fmaxf(sqrtf(bres22[wg][3] + spl[5] * spl[5]), 1e-12f));

    float lsl1 = 0.f, lfl = 0.f, lll = 0.f;
    const int tgt = (pr1 > pr0) ? 1 : 0;
    if (lt < k) {
        float sacc = 0.f, dd, ad;
        dd = h1.x * inv2 - spl[2] * inv2; ad = fabsf(dd);
        sacc += (ad < 1.f) ? 0.5f * dd * dd : ad - 0.5f;
        dd = h1.y * inv3 - spl[3] * inv3; ad = fabsf(dd);
        sacc += (ad < 1.f) ? 0.5f * dd * dd : ad - 0.5f;
        dd = h2.x * inv4 - spl[4] * inv4; ad = fabsf(dd);
        sacc += (ad < 1.f) ? 0.5f * dd * dd : ad - 0.5f;
        dd = h2.y * inv5 - spl[5] * inv5; ad = fabsf(dd);
        sacc += (ad < 1.f) ? 0.5f * dd * dd : ad - 0.5f;
        lsl1 = sacc * 0.25f;
        float x0 = h0.x, x1 = h0.y;
        float mx = fmaxf(x0, x1);
        float lse = mx + logf(expf(x0 - mx) + expf(x1 - mx));
        float logpt = (tgt ? x1 : x0) - lse;
        float pt = expf(logpt);
        lfl = -(1.f - pt) * (1.f - pt) * logpt;
        lll = gLp[si];
    }
    {
        float v;
        v = wsum(lsl1); if (l == 0) wred2[wg][0 * 4 + lw] = v;
        v = wsum(lll);  if (l == 0) wred2[wg][1 * 4 + lw] = v;
        v = wsum(lfl);  if (l == 0) wred2[wg][2 * 4 + lw] = v;
        GBAR();
        if (lt == 0) {
            float ra = 0.f, rb = 0.f, rc = 0.f;
            for (int w = 0; w < 4; ++w) {
                ra += wred2[wg][0 * 4 + w];
                rb += wred2[wg][1 * 4 + w];
                rc += wred2[wg][2 * 4 + w];
            }
            float invk = 1.f / (float)k;
            int task = img * 16 + prior;
            g_part[task * 3 + 0] = ra * invk;
            g_part[task * 3 + 1] = rb * invk;
            g_part[task * 3 + 2] = rc * invk;
        }
    }

    // ---------------- last-CTA final fold
    __syncthreads();
    if (tid == 0) {
        __threadfence();
        unsigned v = atomicAdd(&g_ctr, 1u);
        sAm = (v == NCTA - 1) ? 1u : 0u;
    }
    __syncthreads();
    if (sAm) {
        if (tid == 0) g_ctr = 0;
        __threadfence();
        float a2 = 0.f, b2 = 0.f, c2 = 0.f;
        for (int i = tid; i < 1024; i += NT) {
            a2 += g_part[i * 3 + 0];
            b2 += g_part[i * 3 + 1];
            c2 += g_part[i * 3 + 2];
        }
        float v;
        v = wsum(a2); if (l == 0) wred[0 * 8 + wid] = v;
        v = wsum(b2); if (l == 0) wred[1 * 8 + wid] = v;
        v = wsum(c2); if (l == 0) wred[2 * 8 + wid] = v;
        __syncthreads();
        if (tid == 0) {
            float sa = 0.f, sb = 0.f, sc = 0.f;
            for (int w = 0; w < 8; ++w) {
                sa += wred[0 * 8 + w]; sb += wred[1 * 8 + w]; sc += wred[2 * 8 + w];
            }
            const float inv = 1.f / 1024.f;
            float sl1l = sa * inv, ll = sb * inv, fl = sc * inv;
            out[0] = (sl1l > 0.f ? 0.5f * sl1l : 0.f)
                   + (ll   > 0.f ? 2.0f * ll   : 0.f)
                   + (fl   > 0.f ? 2.0f * fl   : 0.f);
        }
    }
}

extern "C" void kernel_launch(void* const* d_in, const int* in_sizes, int n_in,
                              void* d_out, int out_size)
{
    const float* output = (const float*)d_in[0];  // [64,1000,78]
    const float* label  = (const float*)d_in[1];  // [64,16,78]
    static bool attr_done = false;
    if (!attr_done) {
        cudaFuncSetAttribute(lane_kernel,
                             cudaFuncAttributeMaxDynamicSharedMemorySize,
                             DYN_FLOATS * sizeof(float));
        attr_done = true;
    }
    lane_kernel<<<NCTA, NT, DYN_FLOATS * sizeof(float)>>>(output, label, (float*)d_out);
}

// round 15
// speedup vs baseline: 1.9856x; 1.9856x over previous
#include <cuda_runtime.h>

#define N_ANCH 1000
#define N_FEAT 78
#define NT     256
#define NCTA   512          // 64 images * 8 CTAs; CTA = slice for stage-1, 2 priors for select
#define K_MAX  64
#define FULL   0xffffffffu
#define NIMG   64
#define SLICE  125

__device__ float    gA[(size_t)NIMG * 16 * 1000];
__device__ float    gLiou[(size_t)NIMG * 16 * 1000];
__device__ float    gLogit[(size_t)NIMG * 2 * 1024];
__device__ float    gSums[(size_t)NIMG * 8 * 68];
__device__ float    g_part[1024 * 3];
__device__ unsigned g_ctr;
__device__ unsigned g_imgc[NIMG];

static __device__ __forceinline__ unsigned fkey(float f) {
    unsigned u = __float_as_uint(f);
    return (u & 0x80000000u) ? ~u : (u | 0x80000000u);
}
static __device__ __forceinline__ float wsum(float v) {
    #pragma unroll
    for (int o = 16; o; o >>= 1) v += __shfl_xor_sync(FULL, v, o);
    return v;
}
static __device__ __forceinline__ float wmax(float v) {
    #pragma unroll
    for (int o = 16; o; o >>= 1) v = fmaxf(v, __shfl_xor_sync(FULL, v, o));
    return v;
}
static __device__ __forceinline__ int wscan_incl(int v, int lane) {
    #pragma unroll
    for (int o = 1; o < 32; o <<= 1) {
        int t = __shfl_up_sync(FULL, v, o);
        if (lane >= o) v += t;
    }
    return v;
}

#define GBAR() asm volatile("bar.sync %0, 128;" :: "r"(wg + 1) : "memory")

// dynamic smem layout:
//   Phase A: tile[0..9750)  Lbuf[9760..9760+125*17)  spsm[11888..13168)
//   Phase B: f0s[0..1000) f1s[1000..2000) Acst[2000..4000)   (spsm persists)
#define DYN_FLOATS 13168

__global__ __launch_bounds__(NT, 4)
void lane_kernel(const float* __restrict__ output, const float* __restrict__ label,
                 float* __restrict__ out)
{
    extern __shared__ float dyn[];
    float* tile = dyn;
    float* Lbuf = dyn + 9760;     // stride 17 (conflict-free)
    float* spsm = dyn + 11888;    // 16 priors * stride 80

    __shared__ float wred[12 * 8];
    __shared__ float bres[12];
    __shared__ unsigned sAm;
    __shared__ int   hist2[2][256];
    __shared__ int   iw2[2][4];
    __shared__ int   sel2[2][K_MAX];
    __shared__ int   si22[2][2];
    __shared__ float wred2[2][16];
    __shared__ float bres22[2][4];
    __shared__ int   tbuf[2][64];
    __shared__ int   tcnt[2];

    const int tid = threadIdx.x;
    const int wid = tid >> 5;
    const int l   = tid & 31;
    const int bx  = blockIdx.x;
    const int img = bx >> 3;
    const int sl  = bx & 7;
    const float* feat = output + (size_t)img * (N_ANCH * N_FEAT);

    // ---------------- load 16 priors + own contiguous 125-anchor slice
    for (int idx = tid; idx < 16 * N_FEAT; idx += NT) {
        int p = idx / N_FEAT, j = idx - p * N_FEAT;
        spsm[p * 80 + j] = label[((size_t)img * 16 + p) * N_FEAT + j];
    }
    {
        const float* src = feat + (size_t)sl * (SLICE * N_FEAT);
        for (int idx = tid; idx < SLICE * N_FEAT; idx += NT) tile[idx] = src[idx];
    }
    __syncthreads();

    // ---------------- logits out + slice max
    float m0 = -3.4e38f, m1 = -3.4e38f;
    if (tid < SLICE) {
        float v0 = tile[tid * N_FEAT + 0], v1 = tile[tid * N_FEAT + 1];
        gLogit[((size_t)img * 2 + 0) * 1024 + sl * SLICE + tid] = v0;
        gLogit[((size_t)img * 2 + 1) * 1024 + sl * SLICE + tid] = v1;
        m0 = v0; m1 = v1;
    }
    {
        float v;
        v = wmax(m0); if (l == 0) wred[0 * 8 + wid] = v;
        v = wmax(m1); if (l == 0) wred[1 * 8 + wid] = v;
    }

    // ---------------- L1 for all 16 priors: half-anchor per thread, float2 LDS
    int a = tid >> 1; if (a > SLICE - 1) a = SLICE - 1;
    const int h = tid & 1;
    const int base = 6 + 36 * h;
    float L[16];
    #pragma unroll
    for (int p = 0; p < 16; ++p) L[p] = 0.f;
    {
        const float* row = tile + a * N_FEAT + base;   // even offset -> 8B aligned
        const float* spb = spsm + base;                // stride 80, even -> aligned
        #pragma unroll 6
        for (int j = 0; j < 36; j += 2) {
            float2 v = *(const float2*)(row + j);
            #pragma unroll
            for (int p = 0; p < 8; ++p) {
                float2 s = *(const float2*)(spb + p * 80 + j);
                L[p] += fabsf(v.x - s.x) + fabsf(v.y - s.y);
            }
            #pragma unroll
            for (int p = 8; p < 16; ++p) {
                float2 s = *(const float2*)(spb + p * 80 + j);
                L[p] += fabsf(v.x - s.x) + fabsf(v.y - s.y);
            }
        }
    }
    #pragma unroll
    for (int p = 0; p < 16; ++p) L[p] += __shfl_xor_sync(FULL, L[p], 1);
    if (h == 0 && tid < 2 * SLICE) {
        #pragma unroll
        for (int p = 0; p < 16; ++p) Lbuf[a * 17 + p] = L[p];
    }
    __syncthreads();   // Lbuf + wred(max) visible

    if (tid < 2) {
        float r = wred[tid * 8];
        for (int w = 1; w < 8; ++w) r = fmaxf(r, wred[tid * 8 + w]);
        gSums[((size_t)img * 8 + sl) * 68 + tid] = r;
    }

    // ---------------- per-prior products + slice partial sums (warp w: priors w, w+8)
    {
        #pragma unroll
        for (int pi = 0; pi < 2; ++pi) {
            const int p = wid + 8 * pi;
            const float px = spsm[p * 80 + 3], py = spsm[p * 80 + 4], pt = spsm[p * 80 + 5];
            float sxy = 0.f, sth = 0.f, sdis = 0.f, sliou = 0.f;
            #pragma unroll
            for (int m = 0; m < 4; ++m) {
                int a2 = l + 32 * m;
                if (a2 < SLICE) {
                    float Lv = Lbuf[a2 * 17 + p];
                    float rx = tile[a2 * N_FEAT + 3];
                    float ry = tile[a2 * N_FEAT + 4];
                    float rt = tile[a2 * N_FEAT + 5];
                    float dx = rx - px, dy = ry - py, th = rt - pt;
                    float xy = sqrtf(dx * dx + dy * dy);
                    float dis = Lv * (1.0f / 72.0f);
                    float liou = __fdividef(2.f * Lv + 1e-9f, 2160.f + Lv + 1e-9f);
                    size_t o = ((size_t)img * 16 + p) * 1000 + sl * SLICE + a2;
                    gA[o] = dis * xy * th;
                    gLiou[o] = liou;
                    sxy += xy * xy; sth += th * th; sdis += dis * dis; sliou += liou;
                }
            }
            sxy = wsum(sxy); sth = wsum(sth); sdis = wsum(sdis); sliou = wsum(sliou);
            if (l == 0) {
                float* gs = gSums + ((size_t)img * 8 + sl) * 68 + 2 + p * 4;
                gs[0] = sxy; gs[1] = sth; gs[2] = sdis; gs[3] = sliou;
            }
        }
    }

    // ---------------- per-image generation barrier
    __threadfence();
    __syncthreads();
    if (tid == 0) {
        unsigned old = atomicAdd(&g_imgc[img], 1u);
        unsigned target = ((old >> 3) + 1u) << 3;
        unsigned v;
        do {
            asm volatile("ld.acquire.gpu.u32 %0, [%1];"
                         : "=r"(v) : "l"(g_imgc + img) : "memory");
            if (v >= target) break;
            __nanosleep(40);
        } while (true);
        __threadfence();
    }
    __syncthreads();

    // ================ Phase B: totals, softmax, focal =========================
    float* f0s  = dyn;
    float* f1s  = dyn + 1000;
    float* Acst = dyn + 2000;

    if (tid < 2) {
        float m = -3.4e38f;
        for (int s = 0; s < 8; ++s) m = fmaxf(m, gSums[((size_t)img * 8 + s) * 68 + tid]);
        bres[tid] = m;
    } else if (tid >= 32 && tid < 40) {
        int q = tid - 32;
        int p = 2 * sl + (q >> 2), c = q & 3;
        float t = 0.f;
        for (int s = 0; s < 8; ++s) t += gSums[((size_t)img * 8 + s) * 68 + 2 + p * 4 + c];
        bres[2 + q] = t;
    }
    __syncthreads();
    const float M0 = bres[0], M1 = bres[1];

    const float* gl0 = gLogit + ((size_t)img * 2 + 0) * 1024;
    const float* gl1 = gLogit + ((size_t)img * 2 + 1) * 1024;
    const bool act = (tid < 250);
    float s0 = 0.f, s1 = 0.f;
    if (act) {
        float4 c = ((const float4*)gl0)[tid];
        ((float4*)f0s)[tid] = c;
        s0 = expf(c.x - M0) + expf(c.y - M0) + expf(c.z - M0) + expf(c.w - M0);
        float4 d = ((const float4*)gl1)[tid];
        ((float4*)f1s)[tid] = d;
        s1 = expf(d.x - M1) + expf(d.y - M1) + expf(d.z - M1) + expf(d.w - M1);
    }
    {
        float v;
        v = wsum(s0); if (l == 0) wred[0 * 8 + wid] = v;
        v = wsum(s1); if (l == 0) wred[1 * 8 + wid] = v;
        __syncthreads();
        if (tid < 2) {
            float r = 0.f;
            for (int w = 0; w < 8; ++w) r += wred[tid * 8 + w];
            bres[10 + tid] = r;
        }
        __syncthreads();
    }
    const float lse0 = M0 + logf(bres[10]);
    const float lse1 = M1 + logf(bres[11]);

    if (act) {
        float4 c = ((const float4*)f0s)[tid];
        float ls, e;
        ls = c.x - lse0; e = expf(ls); c.x = (1.f - e) * (1.f - e) * ls;
        ls = c.y - lse0; e = expf(ls); c.y = (1.f - e) * (1.f - e) * ls;
        ls = c.z - lse0; e = expf(ls); c.z = (1.f - e) * (1.f - e) * ls;
        ls = c.w - lse0; e = expf(ls); c.w = (1.f - e) * (1.f - e) * ls;
        ((float4*)f0s)[tid] = c;
        float4 d = ((const float4*)f1s)[tid];
        ls = d.x - lse1; e = expf(ls); d.x = (1.f - e) * (1.f - e) * ls;
        ls = d.y - lse1; e = expf(ls); d.y = (1.f - e) * (1.f - e) * ls;
        ls = d.z - lse1; e = expf(ls); d.z = (1.f - e) * (1.f - e) * ls;
        ls = d.w - lse1; e = expf(ls); d.w = (1.f - e) * (1.f - e) * ls;
        ((float4*)f1s)[tid] = d;
    }
    __syncthreads();

    // ================ SPLIT: group wg handles prior 2*sl+wg ===================
    const int wg = wid >> 2;
    const int lt = tid & 127;
    const int lw = (tid >> 5) & 3;
    const int prior = 2 * sl + wg;

    const float sxy   = bres[2 + wg * 4 + 0];
    const float sth   = bres[2 + wg * 4 + 1];
    const float sdis  = bres[2 + wg * 4 + 2];
    const float sliou = bres[2 + wg * 4 + 3];
    const float Nx  = fmaxf(sqrtf(sxy),  1e-12f);
    const float Nt2 = fmaxf(sqrtf(sth),  1e-12f);
    const float Nd  = fmaxf(sqrtf(sdis), 1e-12f);
    const float invn = 1.f / (Nx * Nt2 * Nd);
    int k = (int)sliou;
    if (k < 1) k = 1;
    if (k > K_MAX) k = K_MAX;
    const float* spl = spsm + prior * 80;
    const float pr0 = spl[0], pr1 = spl[1];
    const float* gAp = gA    + ((size_t)img * 16 + prior) * 1000;
    const float* gLp = gLiou + ((size_t)img * 16 + prior) * 1000;
    float* Ac = Acst + wg * 1000;

    hist2[wg][lt] = 0; hist2[wg][lt + 128] = 0;
    unsigned keys[8];
    #pragma unroll
    for (int q = 0; q < 8; ++q) {
        int i = lt + (q << 7);
        if (i < N_ANCH) {
            float av = gAp[i];
            float t = av * invn;
            float cost = 3.f * t * t + pr0 * f0s[i] + pr1 * f1s[i];
            Ac[i] = cost;
            keys[q] = fkey(cost);
        } else keys[q] = 0xFFFFFFFFu;
    }
    GBAR();

    // ---------------- radix-select k-th smallest (4x8-bit), 2 barriers/pass
    unsigned prefix = 0; int kk = k;
    #pragma unroll
    for (int shift = 24; shift >= 0; shift -= 8) {
        unsigned pmask = (shift == 24) ? 0u : (0xFFFFFFFFu << (shift + 8));
        #pragma unroll
        for (int q = 0; q < 8; ++q) {
            int i = lt + (q << 7);
            if (i < N_ANCH && (keys[q] & pmask) == prefix)
                atomicAdd(&hist2[wg][(keys[q] >> shift) & 255], 1);
        }
        GBAR();
        if (lw == 0) {
            int b[8]; int s = 0;
            #pragma unroll
            for (int t2 = 0; t2 < 8; ++t2) {
                b[t2] = hist2[wg][l * 8 + t2];
                s += b[t2];
                hist2[wg][l * 8 + t2] = 0;
            }
            int incl = wscan_incl(s, l);
            int excl = incl - s;
            if (kk > excl && kk <= incl) {
                int run = excl, bin = -1, rem = 0;
                #pragma unroll
                for (int t2 = 0; t2 < 8; ++t2) {
                    if (bin < 0 && kk <= run + b[t2]) { bin = l * 8 + t2; rem = kk - run; }
                    run += b[t2];
                }
                si22[wg][0] = bin; si22[wg][1] = rem;
            }
        }
        GBAR();
        prefix |= ((unsigned)si22[wg][0]) << shift;
        kk = si22[wg][1];
    }
    const unsigned T = prefix;
    const int rties = kk;

    // ---------------- tie collection (exact semantics)
    if (lt == 0) tcnt[wg] = 0;
    GBAR();
    #pragma unroll
    for (int q = 0; q < 8; ++q) {
        int i = lt + (q << 7);
        if (i < N_ANCH && keys[q] == T) {
            int p = atomicAdd(&tcnt[wg], 1);
            if (p < 64) tbuf[wg][p] = i;
        }
    }
    GBAR();
    const int nt = tcnt[wg];

    auto pick = [&](int q) -> bool {
        int i = lt + (q << 7);
        if (i >= N_ANCH) return false;
        unsigned key = keys[q];
        if (key < T) return true;
        if (key != T) return false;
        int r = 0;
        if (nt <= 64) {
            for (int t2 = 0; t2 < nt; ++t2) r += (tbuf[wg][t2] < i);
        } else {
            for (int j = 0; j < i; ++j) r += (fkey(Ac[j]) == T);
        }
        return r < rties;
    };

    // ---------------- deterministic compaction
    int cnt = 0;
    #pragma unroll
    for (int q = 0; q < 8; ++q) cnt += pick(q) ? 1 : 0;
    {
        int inc = wscan_incl(cnt, l);
        if (l == 31) iw2[wg][lw] = inc;
        GBAR();
        int off = 0;
        #pragma unroll
        for (int w = 0; w < 4; ++w) if (w < lw) off += iw2[wg][w];
        int o = off + inc - cnt;
        #pragma unroll
        for (int q = 0; q < 8; ++q)
            if (pick(q)) sel2[wg][o++] = lt + (q << 7);
    }
    GBAR();

    // ---------------- stage-2: one scattered row read (cols 0..5) + liou gather
    float q2 = 0.f, q3 = 0.f, q4 = 0.f, q5 = 0.f;
    float2 h0, h1, h2;
    int si = 0;
    if (lt < k) {
        si = sel2[wg][lt];
        const float2* row2 = (const float2*)(feat + (size_t)si * N_FEAT);
        h0 = row2[0]; h1 = row2[1]; h2 = row2[2];
        q2 = h1.x * h1.x; q3 = h1.y * h1.y; q4 = h2.x * h2.x; q5 = h2.y * h2.y;
    }
    {
        float v;
        v = wsum(q2); if (l == 0) wred2[wg][0 * 4 + lw] = v;
        v = wsum(q3); if (l == 0) wred2[wg][1 * 4 + lw] = v;
        v = wsum(q4); if (l == 0) wred2[wg][2 * 4 + lw] = v;
        v = wsum(q5); if (l == 0) wred2[wg][3 * 4 + lw] = v;
        GBAR();
        if (lt < 4) {
            float r = 0.f;
            for (int w = 0; w < 4; ++w) r += wred2[wg][lt * 4 + w];
            bres22[wg][lt] = r;
        }
        GBAR();
    }
    const float inv2 = __fdividef(1.f, fmaxf(sqrtf(bres22[wg][0] + spl[2] * spl[2]), 1e-12f));
    const float inv3 = __fdividef(1.f, fmaxf(sqrtf(bres22[wg][1] + spl[3] * spl[3]), 1e-12f));
    const float inv4 = __fdividef(1.f, fmaxf(sqrtf(bres22[wg][2] + spl[4] * spl[4]), 1e-12f));
    const float inv5 = __fdividef(1.f, fmaxf(sqrtf(bres22[wg][3] + spl[5] * spl[5]), 1e-12f));

    float lsl1 = 0.f, lfl = 0.f, lll = 0.f;
    const int tgt = (pr1 > pr0) ? 1 : 0;
    if (lt < k) {
        float sacc = 0.f, dd, ad;
        dd = h1.x * inv2 - spl[2] * inv2; ad = fabsf(dd);
        sacc += (ad < 1.f) ? 0.5f * dd * dd : ad - 0.5f;
        dd = h1.y * inv3 - spl[3] * inv3; ad = fabsf(dd);
        sacc += (ad < 1.f) ? 0.5f * dd * dd : ad - 0.5f;
        dd = h2.x * inv4 - spl[4] * inv4; ad = fabsf(dd);
        sacc += (ad < 1.f) ? 0.5f * dd * dd : ad - 0.5f;
        dd = h2.y * inv5 - spl[5] * inv5; ad = fabsf(dd);
        sacc += (ad < 1.f) ? 0.5f * dd * dd : ad - 0.5f;
        lsl1 = sacc * 0.25f;
        float x0 = h0.x, x1 = h0.y;
        float mx = fmaxf(x0, x1);
        float lse = mx + logf(expf(x0 - mx) + expf(x1 - mx));
        float logpt = (tgt ? x1 : x0) - lse;
        float pt = expf(logpt);
        lfl = -(1.f - pt) * (1.f - pt) * logpt;
        lll = gLp[si];
    }
    {
        float v;
        v = wsum(lsl1); if (l == 0) wred2[wg][0 * 4 + lw] = v;
        v = wsum(lll);  if (l == 0) wred2[wg][1 * 4 + lw] = v;
        v = wsum(lfl);  if (l == 0) wred2[wg][2 * 4 + lw] = v;
        GBAR();
        if (lt == 0) {
            float ra = 0.f, rb = 0.f, rc = 0.f;
            for (int w = 0; w < 4; ++w) {
                ra += wred2[wg][0 * 4 + w];
                rb += wred2[wg][1 * 4 + w];
                rc += wred2[wg][2 * 4 + w];
            }
            float invk = 1.f / (float)k;
            int task = img * 16 + prior;
            g_part[task * 3 + 0] = ra * invk;
            g_part[task * 3 + 1] = rb * invk;
            g_part[task * 3 + 2] = rc * invk;
        }
    }

    // ---------------- last-CTA final fold
    __syncthreads();
    if (tid == 0) {
        __threadfence();
        unsigned v = atomicAdd(&g_ctr, 1u);
        sAm = (v == NCTA - 1) ? 1u : 0u;
    }
    __syncthreads();
    if (sAm) {
        if (tid == 0) g_ctr = 0;
        __threadfence();
        float a2 = 0.f, b2 = 0.f, c2 = 0.f;
        for (int i = tid; i < 1024; i += NT) {
            a2 += g_part[i * 3 + 0];
            b2 += g_part[i * 3 + 1];
            c2 += g_part[i * 3 + 2];
        }
        float v;
        v = wsum(a2); if (l == 0) wred[0 * 8 + wid] = v;
        v = wsum(b2); if (l == 0) wred[1 * 8 + wid] = v;
        v = wsum(c2); if (l == 0) wred[2 * 8 + wid] = v;
        __syncthreads();
        if (tid == 0) {
            float sa = 0.f, sb = 0.f, sc = 0.f;
            for (int w = 0; w < 8; ++w) {
                sa += wred[0 * 8 + w]; sb += wred[1 * 8 + w]; sc += wred[2 * 8 + w];
            }
            const float inv = 1.f / 1024.f;
            float sl1l = sa * inv, ll = sb * inv, fl = sc * inv;
            out[0] = (sl1l > 0.f ? 0.5f * sl1l : 0.f)
                   + (ll   > 0.f ? 2.0f * ll   : 0.f)
                   + (fl   > 0.f ? 2.0f * fl   : 0.f);
        }
    }
}

extern "C" void kernel_launch(void* const* d_in, const int* in_sizes, int n_in,
                              void* d_out, int out_size)
{
    const float* output = (const float*)d_in[0];  // [64,1000,78]
    const float* label  = (const float*)d_in[1];  // [64,16,78]
    static bool attr_done = false;
    if (!attr_done) {
        cudaFuncSetAttribute(lane_kernel,
                             cudaFuncAttributeMaxDynamicSharedMemorySize,
                             DYN_FLOATS * sizeof(float));
        attr_done = true;
    }
    lane_kernel<<<NCTA, NT, DYN_FLOATS * sizeof(float)>>>(output, label, (float*)d_out);
}